// round 2
// baseline (speedup 1.0000x reference)
#include <cuda_runtime.h>
#include <cstdint>

// Problem constants (fixed by the reference)
#define NUM_CLASSES 100000
#define FEAT_DIM    256
#define BATCH       8192
#define ALPHA_C     1.0f
#define EPS_C       1e-6f

// Scratch (no cudaMalloc allowed): per-class counts + double loss accumulator
__device__ int    g_counts[NUM_CLASSES];
__device__ double g_loss;

// ---------------------------------------------------------------------------
// K0: zero the scratch
__global__ void k_zero() {
    int i = blockIdx.x * blockDim.x + threadIdx.x;
    if (i == 0) g_loss = 0.0;
    if (i < NUM_CLASSES) g_counts[i] = 0;
}

// K1: per-class counts (target is int32 on device — harness downcasts int64)
__global__ void k_count(const int* __restrict__ target) {
    int i = blockIdx.x * blockDim.x + threadIdx.x;
    if (i < BATCH) atomicAdd(&g_counts[target[i]], 1);
}

// K2: bulk copy centers -> out_centers (out is float-offset by 1, so scalar
//     coalesced 32-bit traffic; this is the DRAM-dominant kernel)
__global__ void k_copy(const float* __restrict__ src, float* __restrict__ dst) {
    size_t n = (size_t)NUM_CLASSES * FEAT_DIM;
    size_t i = (size_t)blockIdx.x * blockDim.x + threadIdx.x;
    size_t stride = (size_t)gridDim.x * blockDim.x;
    for (; i < n; i += stride) {
        dst[i] = __ldcs(&src[i]);   // streaming load: no reuse of src here
    }
}

// K3: main pass. 64 threads per sample, 4 floats (float4) per thread.
//     blockDim = 256 -> 4 samples per block, 2048 blocks.
__global__ void k_main(const float* __restrict__ features,
                       const int* __restrict__ target,
                       const float* __restrict__ centers,
                       float* __restrict__ out_centers) {
    int sample = blockIdx.x * 4 + (threadIdx.x >> 6);
    int l64    = threadIdx.x & 63;          // 0..63, covers 256 floats

    int t = target[sample];
    float cnt = (float)g_counts[t];
    float scale = ALPHA_C / (cnt + EPS_C);

    const float4 f4 = reinterpret_cast<const float4*>(features + (size_t)sample * FEAT_DIM)[l64];
    const float4 c4 = reinterpret_cast<const float4*>(centers  + (size_t)t      * FEAT_DIM)[l64];

    float dx = c4.x - f4.x;
    float dy = c4.y - f4.y;
    float dz = c4.z - f4.z;
    float dw = c4.w - f4.w;

    float local = dx * dx + dy * dy + dz * dz + dw * dw;

    // scatter-add the negative scaled update into the (already copied) output
    float* dst = out_centers + (size_t)t * FEAT_DIM + (size_t)l64 * 4;
    atomicAdd(dst + 0, -dx * scale);
    atomicAdd(dst + 1, -dy * scale);
    atomicAdd(dst + 2, -dz * scale);
    atomicAdd(dst + 3, -dw * scale);

    // block reduction of the squared-diff sum, double accumulate
    __shared__ float warp_sums[8];
    #pragma unroll
    for (int off = 16; off > 0; off >>= 1)
        local += __shfl_down_sync(0xFFFFFFFFu, local, off);
    int wid = threadIdx.x >> 5;
    int lid = threadIdx.x & 31;
    if (lid == 0) warp_sums[wid] = local;
    __syncthreads();
    if (wid == 0) {
        float v = (lid < 8) ? warp_sums[lid] : 0.0f;
        #pragma unroll
        for (int off = 4; off > 0; off >>= 1)
            v += __shfl_down_sync(0xFFFFFFFFu, v, off);
        if (lid == 0) atomicAdd(&g_loss, (double)v);
    }
}

// K4: finalize the scalar loss
__global__ void k_final(float* __restrict__ out_loss) {
    out_loss[0] = (float)(g_loss / ((double)BATCH * (double)FEAT_DIM));
}

// ---------------------------------------------------------------------------
extern "C" void kernel_launch(void* const* d_in, const int* in_sizes, int n_in,
                              void* d_out, int out_size) {
    const float* features = (const float*)d_in[0];   // [B, D]
    const int*   target   = (const int*)d_in[1];     // [B] (int64 -> int32 by harness)
    const float* centers  = (const float*)d_in[2];   // [C, D]

    float* out = (float*)d_out;
    // layout: [0] = loss scalar, [1 .. 1+C*D) = new_centers
    float* out_centers = out + (size_t)out_size - (size_t)NUM_CLASSES * FEAT_DIM;

    // K0: zero scratch
    k_zero<<<(NUM_CLASSES + 255) / 256, 256>>>();
    // K1: counts
    k_count<<<(BATCH + 255) / 256, 256>>>(target);
    // K2: copy centers -> out (DRAM-dominant)
    k_copy<<<148 * 8, 256>>>(centers, out_centers);
    // K3: gather + loss + scatter update
    k_main<<<BATCH / 4, 256>>>(features, target, centers, out_centers);
    // K4: write scalar loss
    k_final<<<1, 1>>>(out);
}

// round 3
// speedup vs baseline: 1.5702x; 1.5702x over previous
#include <cuda_runtime.h>
#include <cstdint>

#define NUM_CLASSES 100000
#define FEAT_DIM    256
#define BATCH       8192
#define ALPHA_C     1.0f
#define EPS_C       1e-6f

// Scratch (no cudaMalloc allowed)
__device__ int   g_counts[NUM_CLASSES];
__device__ int   g_head[NUM_CLASSES];   // first sample index per class, -1 if none
__device__ int   g_next[BATCH];         // linked list of samples per class
__device__ float g_loss_part[256];

// ---------------------------------------------------------------------------
// K0: zero scratch
__global__ void k_zero() {
    int i = blockIdx.x * blockDim.x + threadIdx.x;
    if (i < 256) g_loss_part[i] = 0.0f;
    if (i < NUM_CLASSES) { g_counts[i] = 0; g_head[i] = -1; }
}

// K1: counts + per-class sample linked lists (8192 cheap atomics)
__global__ void k_build(const int* __restrict__ target) {
    int i = blockIdx.x * blockDim.x + threadIdx.x;
    if (i < BATCH) {
        int t = target[i];
        atomicAdd(&g_counts[t], 1);
        g_next[i] = atomicExch(&g_head[t], i);
    }
}

// K2: fused pass — one warp per class row.
//     out_row = c - scale*(cnt*c - sum_f);  loss += sum_s |c - f_s|^2
//     Strided scalar lanes: lane l owns floats {l, l+32, ..., l+224} of the row
//     -> every LDG/STG warp-instruction is a dense, coalesced 128B access,
//        8 independent loads in flight per warp (MLP=8).
__global__ void __launch_bounds__(256) k_fused(
        const float* __restrict__ features,
        const float* __restrict__ centers,
        float* __restrict__ out_centers) {
    int w    = (blockIdx.x * blockDim.x + threadIdx.x) >> 5;   // row = class
    int lane = threadIdx.x & 31;
    if (w >= NUM_CLASSES) return;

    const float* crow = centers + (size_t)w * FEAT_DIM;
    float c[8];
    #pragma unroll
    for (int j = 0; j < 8; j++)
        c[j] = __ldcs(crow + lane + 32 * j);   // streaming: no reuse

    int cnt = g_counts[w];
    float* drow = out_centers + (size_t)w * FEAT_DIM;

    if (cnt == 0) {
        #pragma unroll
        for (int j = 0; j < 8; j++)
            drow[lane + 32 * j] = c[j];
        return;
    }

    float sumf[8];
    #pragma unroll
    for (int j = 0; j < 8; j++) sumf[j] = 0.0f;
    float loss = 0.0f;

    int s = g_head[w];                // uniform across warp -> no divergence
    while (s >= 0) {
        const float* frow = features + (size_t)s * FEAT_DIM;
        #pragma unroll
        for (int j = 0; j < 8; j++) {
            float f = frow[lane + 32 * j];
            sumf[j] += f;
            float d = c[j] - f;
            loss += d * d;
        }
        s = g_next[s];
    }

    float scale = ALPHA_C / ((float)cnt + EPS_C);
    #pragma unroll
    for (int j = 0; j < 8; j++) {
        float upd = scale * ((float)cnt * c[j] - sumf[j]);
        drow[lane + 32 * j] = c[j] - upd;
    }

    // warp-reduce the row's loss contribution, scatter into 256 slots
    #pragma unroll
    for (int off = 16; off > 0; off >>= 1)
        loss += __shfl_down_sync(0xFFFFFFFFu, loss, off);
    if (lane == 0)
        atomicAdd(&g_loss_part[w & 255], loss);
}

// K3: final loss reduce (256 floats -> double -> scalar)
__global__ void k_final(float* __restrict__ out_loss) {
    __shared__ double sh[8];
    int lane = threadIdx.x & 31;
    int wid  = threadIdx.x >> 5;
    double v = (double)g_loss_part[threadIdx.x];
    #pragma unroll
    for (int off = 16; off > 0; off >>= 1)
        v += __shfl_down_sync(0xFFFFFFFFu, v, off);
    if (lane == 0) sh[wid] = v;
    __syncthreads();
    if (wid == 0) {
        double s = (lane < 8) ? sh[lane] : 0.0;
        #pragma unroll
        for (int off = 4; off > 0; off >>= 1)
            s += __shfl_down_sync(0xFFFFFFFFu, s, off);
        if (lane == 0)
            out_loss[0] = (float)(s / ((double)BATCH * (double)FEAT_DIM));
    }
}

// ---------------------------------------------------------------------------
extern "C" void kernel_launch(void* const* d_in, const int* in_sizes, int n_in,
                              void* d_out, int out_size) {
    const float* features = (const float*)d_in[0];   // [B, D]
    const int*   target   = (const int*)d_in[1];     // [B] (int64 -> int32 on device)
    const float* centers  = (const float*)d_in[2];   // [C, D]

    float* out = (float*)d_out;
    float* out_centers = out + (size_t)out_size - (size_t)NUM_CLASSES * FEAT_DIM;

    k_zero <<<(NUM_CLASSES + 255) / 256, 256>>>();
    k_build<<<(BATCH + 255) / 256, 256>>>(target);
    // one warp per class row: 100000 warps -> 12500 blocks of 256 threads
    k_fused<<<(NUM_CLASSES * 32 + 255) / 256, 256>>>(features, centers, out_centers);
    k_final<<<1, 256>>>(out);
}